// round 15
// baseline (speedup 1.0000x reference)
#include <cuda_runtime.h>
#include <cuda_fp16.h>
#include <cstdint>

// Problem constants
#define BATCH   2
#define SEQ     2048
#define DMODEL  1024
#define NHEADS  16
#define HDIM    64
#define CEXP    92.33248261689366f   // SCALE(=64) * log2(e)
#define NELEM   (BATCH * SEQ * DMODEL)

// Scratch
__device__ __half g_WT_hi[3 * DMODEL * DMODEL];
__device__ __half g_WT_lo[3 * DMODEL * DMODEL];
__device__ __half g_Qh[NELEM];
__device__ __half g_Ql[NELEM];
__device__ __half g_Kh[NELEM];
__device__ __half g_Kl[NELEM];
__device__ __half g_Vh[NELEM];
__device__ unsigned g_ctr_attn;
__device__ unsigned g_ctr_proj;

// ===========================================================================
// Helpers (sm_80-era PTX only)
// ===========================================================================
__device__ __forceinline__ uint32_t smem_u32(const void* p) {
    uint32_t a;
    asm("{ .reg .u64 t; cvta.to.shared.u64 t, %1; cvt.u32.u64 %0, t; }" : "=r"(a) : "l"(p));
    return a;
}
__device__ __forceinline__ void ldm_x4(uint32_t addr, uint32_t* r) {
    asm volatile("ldmatrix.sync.aligned.m8n8.x4.shared.b16 {%0,%1,%2,%3}, [%4];"
                 : "=r"(r[0]), "=r"(r[1]), "=r"(r[2]), "=r"(r[3]) : "r"(addr));
}
__device__ __forceinline__ void ldm_x4t(uint32_t addr, uint32_t* r) {
    asm volatile("ldmatrix.sync.aligned.m8n8.x4.trans.shared.b16 {%0,%1,%2,%3}, [%4];"
                 : "=r"(r[0]), "=r"(r[1]), "=r"(r[2]), "=r"(r[3]) : "r"(addr));
}
__device__ __forceinline__ void mma_f16(float* c, const uint32_t* a, uint32_t b0, uint32_t b1) {
    asm volatile("mma.sync.aligned.m16n8k16.row.col.f32.f16.f16.f32 "
                 "{%0,%1,%2,%3}, {%4,%5,%6,%7}, {%8,%9}, {%0,%1,%2,%3};"
                 : "+f"(c[0]), "+f"(c[1]), "+f"(c[2]), "+f"(c[3])
                 : "r"(a[0]), "r"(a[1]), "r"(a[2]), "r"(a[3]), "r"(b0), "r"(b1));
}
__device__ __forceinline__ uint32_t pack_h2(float p0, float p1) {
    uint32_t h;
    asm("cvt.rn.f16x2.f32 %0, %1, %2;" : "=r"(h) : "f"(p1), "f"(p0));
    return h;
}
__device__ __forceinline__ void split2h(float p0, float p1, uint32_t& hi, uint32_t& lo) {
    uint32_t h = pack_h2(p0, p1);
    float f0, f1;
    asm("{.reg .b16 a,b; mov.b32 {a,b}, %2; cvt.f32.f16 %0, a; cvt.f32.f16 %1, b;}"
        : "=f"(f0), "=f"(f1) : "r"(h));
    hi = h;
    lo = pack_h2(p0 - f0, p1 - f1);
}
__device__ __forceinline__ float ex2(float x) {
    float r;
    asm("ex2.approx.f32 %0, %1;" : "=f"(r) : "f"(x));
    return r;
}
__device__ __forceinline__ uint32_t h2ex2(uint32_t x) {
    uint32_t r;
    asm("ex2.approx.f16x2 %0, %1;" : "=r"(r) : "r"(x));
    return r;
}
__device__ __forceinline__ void cpa16(uint32_t s, const void* g) {
    asm volatile("cp.async.cg.shared.global [%0], [%1], 16;" :: "r"(s), "l"(g));
}
#define CP_COMMIT() asm volatile("cp.async.commit_group;" ::: "memory")
#define CP_WAIT0()  asm volatile("cp.async.wait_group 0;" ::: "memory")

#define ONE2 0x3C003C00u   // fp16x2 {1.0, 1.0}

// ===========================================================================
// W transpose + split-fp16 convert (also resets work-steal counters)
// ===========================================================================
__global__ void wt_convert(const float* __restrict__ Wq, const float* __restrict__ Wk,
                           const float* __restrict__ Wv)
{
    if (blockIdx.x == 0 && blockIdx.y == 0 && blockIdx.z == 0 &&
        threadIdx.x == 0 && threadIdx.y == 0) {
        g_ctr_attn = 0u; g_ctr_proj = 0u;
    }
    __shared__ float tile[32][33];
    const float* W = (blockIdx.z == 0) ? Wq : (blockIdx.z == 1) ? Wk : Wv;
    const int tx = threadIdx.x, ty = threadIdx.y;
    const int k0 = blockIdx.y * 32, n0 = blockIdx.x * 32;
#pragma unroll
    for (int i = 0; i < 4; i++)
        tile[ty + i * 8][tx] = W[(size_t)(k0 + ty + i * 8) * DMODEL + n0 + tx];
    __syncthreads();
    const size_t base = (size_t)blockIdx.z * DMODEL * DMODEL;
#pragma unroll
    for (int i = 0; i < 4; i++) {
        const int n = n0 + ty + i * 8;
        const int k = k0 + tx;
        const float v = tile[tx][ty + i * 8];
        __half h = __float2half_rn(v);
        g_WT_hi[base + (size_t)n * DMODEL + k] = h;
        g_WT_lo[base + (size_t)n * DMODEL + k] = __float2half_rn(v - __half2float(h));
    }
}

// ===========================================================================
// Projection GEMM (round-9 version, exact): fp16 mma, Q/K 3-term, V 1-term.
// ===========================================================================
#define PSTG 40960
#define PROJ_SMEM (2 * PSTG)
#define PROJ_GRID 296
#define PROJ_UNITS 768

__device__ __forceinline__ void store_splitA(const float4* a, char* dst_stage,
                                             uint32_t ldB, int z)
{
    uint32_t hb[8], lb[8];
#pragma unroll
    for (int i = 0; i < 4; i++) {
        split2h(a[i].x, a[i].y, hb[2 * i], lb[2 * i]);
        split2h(a[i].z, a[i].w, hb[2 * i + 1], lb[2 * i + 1]);
    }
    char* dh = dst_stage + ldB;
    ((uint4*)dh)[0] = make_uint4(hb[0], hb[1], hb[2], hb[3]);
    ((uint4*)dh)[1] = make_uint4(hb[4], hb[5], hb[6], hb[7]);
    if (z < 2) {
        char* dl = dst_stage + 10240 + ldB;
        ((uint4*)dl)[0] = make_uint4(lb[0], lb[1], lb[2], lb[3]);
        ((uint4*)dl)[1] = make_uint4(lb[4], lb[5], lb[6], lb[7]);
    }
}

__global__ __launch_bounds__(256, 2) void proj_mma(const float* __restrict__ qi,
                                                   const float* __restrict__ ki,
                                                   const float* __restrict__ vi)
{
    extern __shared__ char smc[];
    const uint32_t sb = smem_u32(smc);
    int* su = (int*)(smc + 64);
    const int tid = threadIdx.x;
    const int lane = tid & 31;
    const int wid = tid >> 5;
    const int g = lane >> 2, t4 = lane & 3;
    const int wm = wid & 3, wn = wid >> 2;

    const uint32_t aBase = (uint32_t)(wm * 32 + (lane & 15)) * 80 + (lane >> 4) * 16;
    const uint32_t bBase = (uint32_t)(wn * 64 + (lane & 7) + ((lane >> 4) << 3)) * 80
                           + ((lane >> 3) & 1) * 16;
    const int lr = tid >> 1, lq = tid & 1;
    const uint32_t ldB = lr * 80 + lq * 32;

    while (true) {
        if (tid == 0) *su = (int)atomicAdd(&g_ctr_proj, 1u);
        __syncthreads();
        const int u = *su;
        if (u >= PROJ_UNITS) break;

        const int z = u >> 8;
        const int rem = u & 255;
        const int m0 = (rem >> 3) * 128;
        const int n0 = (rem & 7) * 128;

        const float* A;
        __half *Ch, *Cl;
        if (z == 0)      { A = qi; Ch = g_Qh; Cl = g_Ql; }
        else if (z == 1) { A = ki; Ch = g_Kh; Cl = g_Kl; }
        else             { A = vi; Ch = g_Vh; Cl = 0; }
        const size_t woff = (size_t)z * DMODEL * DMODEL;
        const char* BhG = (const char*)(g_WT_hi + woff);
        const char* BlG = (const char*)(g_WT_lo + woff);
        const size_t aRow = (size_t)(m0 + lr) * DMODEL;
        const size_t bRowB = (size_t)(n0 + lr) * DMODEL * 2;

        float c[2][8][4];
#pragma unroll
        for (int mb = 0; mb < 2; mb++)
#pragma unroll
            for (int j = 0; j < 8; j++)
#pragma unroll
                for (int i = 0; i < 4; i++) c[mb][j][i] = 0.0f;

        float4 a[4];
#pragma unroll
        for (int i = 0; i < 4; i++)
            a[i] = ((const float4*)(A + aRow + lq * 16))[i];
#pragma unroll
        for (int j = 0; j < 2; j++) {
            cpa16(sb + 20480 + ldB + j * 16, BhG + bRowB + lq * 32 + j * 16);
            if (z < 2)
                cpa16(sb + 30720 + ldB + j * 16, BlG + bRowB + lq * 32 + j * 16);
        }
        CP_COMMIT();
        store_splitA(a, smc, ldB, z);
        CP_WAIT0();
        __syncthreads();

        for (int kb = 0; kb < 32; kb++) {
            const uint32_t stg = (uint32_t)(kb & 1) * PSTG;
            const bool more = (kb + 1 < 32);
            if (more) {
                const int ko = (kb + 1) * 32;
#pragma unroll
                for (int i = 0; i < 4; i++)
                    a[i] = ((const float4*)(A + aRow + ko + lq * 16))[i];
                const uint32_t ns = sb + (uint32_t)((kb + 1) & 1) * PSTG;
#pragma unroll
                for (int j = 0; j < 2; j++) {
                    cpa16(ns + 20480 + ldB + j * 16, BhG + bRowB + ko * 2 + lq * 32 + j * 16);
                    if (z < 2)
                        cpa16(ns + 30720 + ldB + j * 16, BlG + bRowB + ko * 2 + lq * 32 + j * 16);
                }
                CP_COMMIT();
            }

#pragma unroll
            for (int c2 = 0; c2 < 2; c2++) {
                uint32_t ah[2][4], al[2][4];
#pragma unroll
                for (int mb = 0; mb < 2; mb++) {
                    ldm_x4(sb + stg + aBase + mb * 1280 + c2 * 32, ah[mb]);
                    if (z < 2)
                        ldm_x4(sb + stg + 10240 + aBase + mb * 1280 + c2 * 32, al[mb]);
                }
#pragma unroll
                for (int jj = 0; jj < 4; jj++) {
                    uint32_t r4[4];
                    ldm_x4(sb + stg + 20480 + bBase + jj * 1280 + c2 * 32, r4);
#pragma unroll
                    for (int mb = 0; mb < 2; mb++) {
                        mma_f16(c[mb][2 * jj], ah[mb], r4[0], r4[1]);
                        mma_f16(c[mb][2 * jj + 1], ah[mb], r4[2], r4[3]);
                        if (z < 2) {
                            mma_f16(c[mb][2 * jj], al[mb], r4[0], r4[1]);
                            mma_f16(c[mb][2 * jj + 1], al[mb], r4[2], r4[3]);
                        }
                    }
                }
                if (z < 2) {
#pragma unroll
                    for (int jj = 0; jj < 4; jj++) {
                        uint32_t r4[4];
                        ldm_x4(sb + stg + 30720 + bBase + jj * 1280 + c2 * 32, r4);
#pragma unroll
                        for (int mb = 0; mb < 2; mb++) {
                            mma_f16(c[mb][2 * jj], ah[mb], r4[0], r4[1]);
                            mma_f16(c[mb][2 * jj + 1], ah[mb], r4[2], r4[3]);
                        }
                    }
                }
            }

            if (more) {
                store_splitA(a, smc + (size_t)((kb + 1) & 1) * PSTG, ldB, z);
                CP_WAIT0();
                __syncthreads();
            }
        }

        // epilogue
#pragma unroll
        for (int mb = 0; mb < 2; mb++) {
#pragma unroll
            for (int j = 0; j < 8; j++) {
                const int R0 = m0 + wm * 32 + mb * 16 + g;
                const int col = n0 + wn * 64 + 8 * j + 2 * t4;
                if (z < 2) {
                    uint32_t hi, lo;
                    split2h(c[mb][j][0], c[mb][j][1], hi, lo);
                    *(uint32_t*)(Ch + (size_t)R0 * DMODEL + col) = hi;
                    *(uint32_t*)(Cl + (size_t)R0 * DMODEL + col) = lo;
                    split2h(c[mb][j][2], c[mb][j][3], hi, lo);
                    *(uint32_t*)(Ch + (size_t)(R0 + 8) * DMODEL + col) = hi;
                    *(uint32_t*)(Cl + (size_t)(R0 + 8) * DMODEL + col) = lo;
                } else {
                    *(uint32_t*)(Ch + (size_t)R0 * DMODEL + col) =
                        pack_h2(c[mb][j][0], c[mb][j][1]);
                    *(uint32_t*)(Ch + (size_t)(R0 + 8) * DMODEL + col) =
                        pack_h2(c[mb][j][2], c[mb][j][3]);
                }
            }
        }
    }
}

// ===========================================================================
// Flash attention: 128 threads (4 warps), warp tile = 32 Q-rows x 64 K-cols
// (doubles mma per ldm byte -> halves smem-crossbar pressure per mma).
// 2 CTAs/SM (8 warps, 256-reg budget -> no spills). Q-tile 128 rows.
// smem: QH 0, QL 18432; stage s at 36864 + s*27648 {KH, KL +9216, VH +18432}.
// ===========================================================================
#define A_QL    18432
#define A_STG0  36864
#define A_STGSZ 27648
#define ATTN_SMEM 92160
#define ATTN_GRID 296
#define ATTN_UNITS 512

__global__ __launch_bounds__(128, 2) void attn_mma(float* __restrict__ out)
{
    extern __shared__ char smc[];
    const uint32_t sb = smem_u32(smc);
    int* su = (int*)(smc + 128);   // QH row-0 pad hole (144B stride, 128B data)
    const int tid = threadIdx.x;
    const int lane = tid & 31;
    const int w = tid >> 5;        // 0..3; warp rows 32w..32w+31
    const int g = lane >> 2, t4 = lane & 3;
    const int lrk = tid >> 1, lqk = tid & 1;
    const uint32_t ldKV = lrk * 144 + lqk * 64;

    const uint32_t qB0 = (uint32_t)(32 * w + (lane & 15)) * 144 + (lane >> 4) * 16;
    const uint32_t qB1 = qB0 + 16 * 144;
    const uint32_t kBase = (uint32_t)((lane & 7) + ((lane >> 4) << 3)) * 144
                           + ((lane >> 3) & 1) * 16;
    const uint32_t vBase = (uint32_t)((lane & 7) + (((lane >> 3) & 1) << 3)) * 144
                           + (lane >> 4) * 16;

    while (true) {
        if (tid == 0) *su = (int)atomicAdd(&g_ctr_attn, 1u);
        __syncthreads();
        const int u = *su;
        if (u >= ATTN_UNITS) break;

        const int b = u >> 8;
        const int h = (u >> 4) & 15;
        const int q0 = (u & 15) * 128;
        const int hoff = h * HDIM;

        // prologue: Q (2 planes; 1 row/thread) + KV tile 0 -> stage 0
        {
            const size_t gQ = ((size_t)(b * SEQ + q0 + tid) * DMODEL + hoff) * 2;
            const size_t gB = ((size_t)(b * SEQ + lrk) * DMODEL + hoff) * 2 + lqk * 64;
            const uint32_t dQ = sb + tid * 144;
            const uint32_t dKV = sb + A_STG0 + ldKV;
#pragma unroll
            for (int i = 0; i < 8; i++) {
                cpa16(dQ + i * 16,        (const char*)g_Qh + gQ + i * 16);
                cpa16(dQ + A_QL + i * 16, (const char*)g_Ql + gQ + i * 16);
            }
#pragma unroll
            for (int i = 0; i < 4; i++) {
                cpa16(dKV + i * 16,         (const char*)g_Kh + gB + i * 16);
                cpa16(dKV + 9216 + i * 16,  (const char*)g_Kl + gB + i * 16);
                cpa16(dKV + 18432 + i * 16, (const char*)g_Vh + gB + i * 16);
            }
            CP_COMMIT();
        }
        CP_WAIT0();
        __syncthreads();

        float mA0 = -1e30f, mA1 = -1e30f, mB0 = -1e30f, mB1 = -1e30f;
        float O0[8][4], O1[8][4], lacc0[4], lacc1[4];
#pragma unroll
        for (int j = 0; j < 8; j++)
#pragma unroll
            for (int i = 0; i < 4; i++) { O0[j][i] = 0.0f; O1[j][i] = 0.0f; }
#pragma unroll
        for (int i = 0; i < 4; i++) { lacc0[i] = 0.0f; lacc1[i] = 0.0f; }

        for (int kt = 0; kt < SEQ / 64; kt++) {
            const uint32_t kv = sb + A_STG0 + (uint32_t)(kt & 1) * A_STGSZ;

            if (kt + 1 < SEQ / 64) {
                const size_t gB = ((size_t)(b * SEQ + (kt + 1) * 64 + lrk) * DMODEL + hoff) * 2 + lqk * 64;
                const uint32_t d = sb + A_STG0 + (uint32_t)((kt + 1) & 1) * A_STGSZ + ldKV;
#pragma unroll
                for (int i = 0; i < 4; i++) {
                    cpa16(d + i * 16,         (const char*)g_Kh + gB + i * 16);
                    cpa16(d + 9216 + i * 16,  (const char*)g_Kl + gB + i * 16);
                    cpa16(d + 18432 + i * 16, (const char*)g_Vh + gB + i * 16);
                }
                CP_COMMIT();
            }

            // ---- S (scoped) -> P packed fp16 + alphas, for both row-blocks ----
            uint32_t P0[8][2], P1[8][2];
            float alA0, alA1, alB0, alB1;
            {
                float S0[8][4], S1[8][4];
#pragma unroll
                for (int j = 0; j < 8; j++)
#pragma unroll
                    for (int i = 0; i < 4; i++) { S0[j][i] = 0.0f; S1[j][i] = 0.0f; }

#pragma unroll
                for (int c = 0; c < 4; c++) {
                    uint32_t aqh0[4], aql0[4], aqh1[4], aql1[4];
                    ldm_x4(sb + qB0 + c * 32, aqh0);
                    ldm_x4(sb + A_QL + qB0 + c * 32, aql0);
                    ldm_x4(sb + qB1 + c * 32, aqh1);
                    ldm_x4(sb + A_QL + qB1 + c * 32, aql1);
#pragma unroll
                    for (int jj = 0; jj < 4; jj++) {
                        uint32_t kh[4], kl[4];
                        ldm_x4(kv + kBase + jj * 2304 + c * 32, kh);
                        ldm_x4(kv + 9216 + kBase + jj * 2304 + c * 32, kl);
                        // row-block 0
                        mma_f16(S0[2 * jj], aqh0, kh[0], kh[1]);
                        mma_f16(S0[2 * jj + 1], aqh0, kh[2], kh[3]);
                        mma_f16(S0[2 * jj], aql0, kh[0], kh[1]);
                        mma_f16(S0[2 * jj + 1], aql0, kh[2], kh[3]);
                        mma_f16(S0[2 * jj], aqh0, kl[0], kl[1]);
                        mma_f16(S0[2 * jj + 1], aqh0, kl[2], kl[3]);
                        // row-block 1 (same K fragments)
                        mma_f16(S1[2 * jj], aqh1, kh[0], kh[1]);
                        mma_f16(S1[2 * jj + 1], aqh1, kh[2], kh[3]);
                        mma_f16(S1[2 * jj], aql1, kh[0], kh[1]);
                        mma_f16(S1[2 * jj + 1], aql1, kh[2], kh[3]);
                        mma_f16(S1[2 * jj], aqh1, kl[0], kl[1]);
                        mma_f16(S1[2 * jj + 1], aqh1, kl[2], kl[3]);
                    }
                }

                // softmax row-block 0
                {
                    float mx0 = -1e30f, mx1 = -1e30f;
#pragma unroll
                    for (int j = 0; j < 8; j++) {
                        mx0 = fmaxf(mx0, fmaxf(S0[j][0], S0[j][1]));
                        mx1 = fmaxf(mx1, fmaxf(S0[j][2], S0[j][3]));
                    }
                    mx0 = fmaxf(mx0, __shfl_xor_sync(0xffffffffu, mx0, 1));
                    mx0 = fmaxf(mx0, __shfl_xor_sync(0xffffffffu, mx0, 2));
                    mx1 = fmaxf(mx1, __shfl_xor_sync(0xffffffffu, mx1, 1));
                    mx1 = fmaxf(mx1, __shfl_xor_sync(0xffffffffu, mx1, 2));
                    const float mn0 = fmaxf(mA0, mx0), mn1 = fmaxf(mA1, mx1);
                    alA0 = ex2((mA0 - mn0) * CEXP);
                    alA1 = ex2((mA1 - mn1) * CEXP);
                    mA0 = mn0; mA1 = mn1;
                    const float mc0 = mA0 * CEXP;
                    const float mc1 = mA1 * CEXP;
#pragma unroll
                    for (int j = 0; j < 8; j++) {
                        float x0 = fmaf(S0[j][0], CEXP, -mc0);
                        float x1 = fmaf(S0[j][1], CEXP, -mc0);
                        float x2 = fmaf(S0[j][2], CEXP, -mc1);
                        float x3 = fmaf(S0[j][3], CEXP, -mc1);
                        P0[j][0] = h2ex2(pack_h2(x0, x1));
                        P0[j][1] = h2ex2(pack_h2(x2, x3));
                    }
                }
                // softmax row-block 1
                {
                    float mx0 = -1e30f, mx1 = -1e30f;
#pragma unroll
                    for (int j = 0; j < 8; j++) {
                        mx0 = fmaxf(mx0, fmaxf(S1[j][0], S1[j][1]));
                        mx1 = fmaxf(mx1, fmaxf(S1[j][2], S1[j][3]));
                    }
                    mx0 = fmaxf(mx0, __shfl_xor_sync(0xffffffffu, mx0, 1));
                    mx0 = fmaxf(mx0, __shfl_xor_sync(0xffffffffu, mx0, 2));
                    mx1 = fmaxf(mx1, __shfl_xor_sync(0xffffffffu, mx1, 1));
                    mx1 = fmaxf(mx1, __shfl_xor_sync(0xffffffffu, mx1, 2));
                    const float mn0 = fmaxf(mB0, mx0), mn1 = fmaxf(mB1, mx1);
                    alB0 = ex2((mB0 - mn0) * CEXP);
                    alB1 = ex2((mB1 - mn1) * CEXP);
                    mB0 = mn0; mB1 = mn1;
                    const float mc0 = mB0 * CEXP;
                    const float mc1 = mB1 * CEXP;
#pragma unroll
                    for (int j = 0; j < 8; j++) {
                        float x0 = fmaf(S1[j][0], CEXP, -mc0);
                        float x1 = fmaf(S1[j][1], CEXP, -mc0);
                        float x2 = fmaf(S1[j][2], CEXP, -mc1);
                        float x3 = fmaf(S1[j][3], CEXP, -mc1);
                        P1[j][0] = h2ex2(pack_h2(x0, x1));
                        P1[j][1] = h2ex2(pack_h2(x2, x3));
                    }
                }
            }   // S dead here

#pragma unroll
            for (int j = 0; j < 8; j++) {
                O0[j][0] *= alA0; O0[j][1] *= alA0;
                O0[j][2] *= alA1; O0[j][3] *= alA1;
                O1[j][0] *= alB0; O1[j][1] *= alB0;
                O1[j][2] *= alB1; O1[j][3] *= alB1;
            }
            lacc0[0] *= alA0; lacc0[1] *= alA0;
            lacc0[2] *= alA1; lacc0[3] *= alA1;
            lacc1[0] *= alB0; lacc1[1] *= alB0;
            lacc1[2] *= alB1; lacc1[3] *= alB1;

            // ---- O += P V ; l += P @ ones  (V fragments shared by both blocks) ----
#pragma unroll
            for (int c = 0; c < 4; c++) {
                uint32_t ph0[4], ph1[4];
                ph0[0] = P0[2 * c][0]; ph0[1] = P0[2 * c][1];
                ph0[2] = P0[2 * c + 1][0]; ph0[3] = P0[2 * c + 1][1];
                ph1[0] = P1[2 * c][0]; ph1[1] = P1[2 * c][1];
                ph1[2] = P1[2 * c + 1][0]; ph1[3] = P1[2 * c + 1][1];
                mma_f16(lacc0, ph0, ONE2, ONE2);
                mma_f16(lacc1, ph1, ONE2, ONE2);
#pragma unroll
                for (int jj = 0; jj < 4; jj++) {
                    uint32_t r4[4];
                    ldm_x4t(kv + 18432 + vBase + c * 2304 + jj * 32, r4);
                    mma_f16(O0[2 * jj], ph0, r4[0], r4[1]);
                    mma_f16(O0[2 * jj + 1], ph0, r4[2], r4[3]);
                    mma_f16(O1[2 * jj], ph1, r4[0], r4[1]);
                    mma_f16(O1[2 * jj + 1], ph1, r4[2], r4[3]);
                }
            }

            if (kt + 1 < SEQ / 64) {
                CP_WAIT0();
                __syncthreads();
            }
        }

        // ---- epilogue (both row-blocks) ----
        {
            const float iA0 = 1.0f / lacc0[0];
            const float iA1 = 1.0f / lacc0[2];
            const float iB0 = 1.0f / lacc1[0];
            const float iB1 = 1.0f / lacc1[2];
            const size_t RA = (size_t)(b * SEQ + q0 + 32 * w + g);
            const size_t RB = RA + 16;
#pragma unroll
            for (int j = 0; j < 8; j++) {
                const int col = hoff + 8 * j + 2 * t4;
                *(float2*)&out[RA * DMODEL + col] = make_float2(O0[j][0] * iA0, O0[j][1] * iA0);
                *(float2*)&out[(RA + 8) * DMODEL + col] = make_float2(O0[j][2] * iA1, O0[j][3] * iA1);
                *(float2*)&out[RB * DMODEL + col] = make_float2(O1[j][0] * iB0, O1[j][1] * iB0);
                *(float2*)&out[(RB + 8) * DMODEL + col] = make_float2(O1[j][2] * iB1, O1[j][3] * iB1);
            }
        }
    }
}

// ===========================================================================
// kernel_launch
// ===========================================================================
extern "C" void kernel_launch(void* const* d_in, const int* in_sizes, int n_in,
                              void* d_out, int out_size)
{
    const float* q  = (const float*)d_in[0];
    const float* k  = (const float*)d_in[1];
    const float* v  = (const float*)d_in[2];
    const float* Wq = (const float*)d_in[3];
    const float* Wk = (const float*)d_in[4];
    const float* Wv = (const float*)d_in[5];
    float* out = (float*)d_out;

    wt_convert<<<dim3(32, 32, 3), dim3(32, 8)>>>(Wq, Wk, Wv);

    cudaFuncSetAttribute(proj_mma, cudaFuncAttributeMaxDynamicSharedMemorySize, PROJ_SMEM);
    proj_mma<<<PROJ_GRID, 256, PROJ_SMEM>>>(q, k, v);

    cudaFuncSetAttribute(attn_mma, cudaFuncAttributeMaxDynamicSharedMemorySize, ATTN_SMEM);
    attn_mma<<<ATTN_GRID, 128, ATTN_SMEM>>>(out);
}

// round 16
// speedup vs baseline: 1.0803x; 1.0803x over previous
#include <cuda_runtime.h>
#include <cuda_fp16.h>
#include <cstdint>

// Problem constants
#define BATCH   2
#define SEQ     2048
#define DMODEL  1024
#define NHEADS  16
#define HDIM    64
#define CEXP    92.33248261689366f   // SCALE(=64) * log2(e)
#define NELEM   (BATCH * SEQ * DMODEL)

// Scratch
__device__ __half g_WT_hi[3 * DMODEL * DMODEL];
__device__ __half g_WT_lo[3 * DMODEL * DMODEL];
__device__ __half g_Qh[NELEM];
__device__ __half g_Ql[NELEM];
__device__ __half g_Kh[NELEM];
__device__ __half g_Kl[NELEM];
__device__ __half g_Vh[NELEM];
__device__ unsigned g_ctr;        // pooled work queue
__device__ unsigned g_bar_w;      // global barrier after W phase
__device__ unsigned g_done[16];   // proj completion per (nb, batch), target 48
__device__ unsigned g_fin;        // finish counter (self-reset)

// ===========================================================================
// Helpers (sm_80-era PTX only)
// ===========================================================================
__device__ __forceinline__ uint32_t smem_u32(const void* p) {
    uint32_t a;
    asm("{ .reg .u64 t; cvta.to.shared.u64 t, %1; cvt.u32.u64 %0, t; }" : "=r"(a) : "l"(p));
    return a;
}
__device__ __forceinline__ void ldm_x4(uint32_t addr, uint32_t* r) {
    asm volatile("ldmatrix.sync.aligned.m8n8.x4.shared.b16 {%0,%1,%2,%3}, [%4];"
                 : "=r"(r[0]), "=r"(r[1]), "=r"(r[2]), "=r"(r[3]) : "r"(addr));
}
__device__ __forceinline__ void ldm_x4t(uint32_t addr, uint32_t* r) {
    asm volatile("ldmatrix.sync.aligned.m8n8.x4.trans.shared.b16 {%0,%1,%2,%3}, [%4];"
                 : "=r"(r[0]), "=r"(r[1]), "=r"(r[2]), "=r"(r[3]) : "r"(addr));
}
__device__ __forceinline__ void mma_f16(float* c, const uint32_t* a, uint32_t b0, uint32_t b1) {
    asm volatile("mma.sync.aligned.m16n8k16.row.col.f32.f16.f16.f32 "
                 "{%0,%1,%2,%3}, {%4,%5,%6,%7}, {%8,%9}, {%0,%1,%2,%3};"
                 : "+f"(c[0]), "+f"(c[1]), "+f"(c[2]), "+f"(c[3])
                 : "r"(a[0]), "r"(a[1]), "r"(a[2]), "r"(a[3]), "r"(b0), "r"(b1));
}
__device__ __forceinline__ uint32_t pack_h2(float p0, float p1) {
    uint32_t h;
    asm("cvt.rn.f16x2.f32 %0, %1, %2;" : "=r"(h) : "f"(p1), "f"(p0));
    return h;
}
__device__ __forceinline__ void split2h(float p0, float p1, uint32_t& hi, uint32_t& lo) {
    uint32_t h = pack_h2(p0, p1);
    float f0, f1;
    asm("{.reg .b16 a,b; mov.b32 {a,b}, %2; cvt.f32.f16 %0, a; cvt.f32.f16 %1, b;}"
        : "=f"(f0), "=f"(f1) : "r"(h));
    hi = h;
    lo = pack_h2(p0 - f0, p1 - f1);
}
__device__ __forceinline__ float ex2(float x) {
    float r;
    asm("ex2.approx.f32 %0, %1;" : "=f"(r) : "f"(x));
    return r;
}
__device__ __forceinline__ uint32_t h2ex2(uint32_t x) {
    uint32_t r;
    asm("ex2.approx.f16x2 %0, %1;" : "=r"(r) : "r"(x));
    return r;
}
__device__ __forceinline__ void cpa16(uint32_t s, const void* g) {
    asm volatile("cp.async.cg.shared.global [%0], [%1], 16;" :: "r"(s), "l"(g));
}
#define CP_COMMIT() asm volatile("cp.async.commit_group;" ::: "memory")
#define CP_WAIT0()  asm volatile("cp.async.wait_group 0;" ::: "memory")

#define ONE2 0x3C003C00u   // fp16x2 {1.0, 1.0}

// Proj smem layout: AH 0, AL 10240, BH 20480, BL 30720; stage size 40960
#define PSTG    40960
// Attn smem layout: QH 0, QL 18432; stage s at 36864 + s*27648 {KH, KL+9216, VH+18432}
#define A_QL    18432
#define A_STG0  36864
#define A_STGSZ 27648
#define FUSED_SMEM 92176
#define SU_OFF  92160

#define N_PROJ  768
#define N_UNITS 1280

__device__ __forceinline__ void store_splitA(const float4* a, char* dst_stage,
                                             uint32_t ldB, int z)
{
    uint32_t hb[8], lb[8];
#pragma unroll
    for (int i = 0; i < 4; i++) {
        split2h(a[i].x, a[i].y, hb[2 * i], lb[2 * i]);
        split2h(a[i].z, a[i].w, hb[2 * i + 1], lb[2 * i + 1]);
    }
    char* dh = dst_stage + ldB;
    ((uint4*)dh)[0] = make_uint4(hb[0], hb[1], hb[2], hb[3]);
    ((uint4*)dh)[1] = make_uint4(hb[4], hb[5], hb[6], hb[7]);
    if (z < 2) {
        char* dl = dst_stage + 10240 + ldB;
        ((uint4*)dl)[0] = make_uint4(lb[0], lb[1], lb[2], lb[3]);
        ((uint4*)dl)[1] = make_uint4(lb[4], lb[5], lb[6], lb[7]);
    }
}

// ===========================================================================
// Fused persistent kernel: W-convert phase -> global barrier -> pooled queue
// (768 proj units nb-major, then 512 attn units nb-major with per-(nb,b) deps).
// 256 threads, 2 CTAs/SM, all CTAs co-resident (grid = 2 * SM count).
// ===========================================================================
__global__ __launch_bounds__(256, 2) void fused_mma(
    const float* __restrict__ qi, const float* __restrict__ ki,
    const float* __restrict__ vi,
    const float* __restrict__ Wq, const float* __restrict__ Wk,
    const float* __restrict__ Wv, float* __restrict__ out)
{
    extern __shared__ char smc[];
    const uint32_t sb = smem_u32(smc);
    int* suq = (int*)(smc + SU_OFF);
    const int tid = threadIdx.x;
    const int lane = tid & 31;
    const int wid = tid >> 5;
    const int g = lane >> 2, t4 = lane & 3;

    // ---------------- Phase 0: W transpose + split-fp16 ----------------
    {
        float (*tile)[33] = (float(*)[33])smc;
        const int tx = tid & 31, ty = tid >> 5;
        for (int t = blockIdx.x; t < 3072; t += gridDim.x) {
            const int z = t >> 10;
            const int rem = t & 1023;
            const int k0 = (rem >> 5) * 32;
            const int n0 = (rem & 31) * 32;
            const float* W = (z == 0) ? Wq : (z == 1) ? Wk : Wv;
            __syncthreads();
#pragma unroll
            for (int i = 0; i < 4; i++)
                tile[ty + i * 8][tx] = W[(size_t)(k0 + ty + i * 8) * DMODEL + n0 + tx];
            __syncthreads();
            const size_t base = (size_t)z * DMODEL * DMODEL;
#pragma unroll
            for (int i = 0; i < 4; i++) {
                const int n = n0 + ty + i * 8;
                const int k = k0 + tx;
                const float v = tile[tx][ty + i * 8];
                __half h = __float2half_rn(v);
                g_WT_hi[base + (size_t)n * DMODEL + k] = h;
                g_WT_lo[base + (size_t)n * DMODEL + k] = __float2half_rn(v - __half2float(h));
            }
        }
        __threadfence();
        __syncthreads();
        if (tid == 0) {
            atomicAdd(&g_bar_w, 1u);
            while (*(volatile unsigned*)&g_bar_w < (unsigned)gridDim.x) {}
        }
        __syncthreads();
    }

    // ---------------- Pooled work queue ----------------
    while (true) {
        if (tid == 0) *suq = (int)atomicAdd(&g_ctr, 1u);
        __syncthreads();
        const int u = *suq;
        if (u >= N_UNITS) break;

        if (u < N_PROJ) {
            // ============== PROJ unit (128m x 128n x 1024k), nb-major ==============
            const int nb = u / 96;
            const int r = u - nb * 96;
            const int z = r >> 5;
            const int mb = r & 31;
            const int m0 = mb * 128;
            const int n0 = nb * 128;

            const int wm = wid & 3, wn = wid >> 2;
            const uint32_t aBase = (uint32_t)(wm * 32 + (lane & 15)) * 80 + (lane >> 4) * 16;
            const uint32_t bBase = (uint32_t)(wn * 64 + (lane & 7) + ((lane >> 4) << 3)) * 80
                                   + ((lane >> 3) & 1) * 16;
            const int lr = tid >> 1, lq = tid & 1;
            const uint32_t ldB = lr * 80 + lq * 32;

            const float* A;
            __half *Ch, *Cl;
            if (z == 0)      { A = qi; Ch = g_Qh; Cl = g_Ql; }
            else if (z == 1) { A = ki; Ch = g_Kh; Cl = g_Kl; }
            else             { A = vi; Ch = g_Vh; Cl = 0; }
            const size_t woff = (size_t)z * DMODEL * DMODEL;
            const char* BhG = (const char*)(g_WT_hi + woff);
            const char* BlG = (const char*)(g_WT_lo + woff);
            const size_t aRow = (size_t)(m0 + lr) * DMODEL;
            const size_t bRowB = (size_t)(n0 + lr) * DMODEL * 2;

            float c[2][8][4];
#pragma unroll
            for (int mb2 = 0; mb2 < 2; mb2++)
#pragma unroll
                for (int j = 0; j < 8; j++)
#pragma unroll
                    for (int i = 0; i < 4; i++) c[mb2][j][i] = 0.0f;

            float4 a[4];
#pragma unroll
            for (int i = 0; i < 4; i++)
                a[i] = ((const float4*)(A + aRow + lq * 16))[i];
#pragma unroll
            for (int j = 0; j < 2; j++) {
                cpa16(sb + 20480 + ldB + j * 16, BhG + bRowB + lq * 32 + j * 16);
                if (z < 2)
                    cpa16(sb + 30720 + ldB + j * 16, BlG + bRowB + lq * 32 + j * 16);
            }
            CP_COMMIT();
            store_splitA(a, smc, ldB, z);
            CP_WAIT0();
            __syncthreads();

            for (int kb = 0; kb < 32; kb++) {
                const uint32_t stg = (uint32_t)(kb & 1) * PSTG;
                const bool more = (kb + 1 < 32);
                if (more) {
                    const int ko = (kb + 1) * 32;
#pragma unroll
                    for (int i = 0; i < 4; i++)
                        a[i] = ((const float4*)(A + aRow + ko + lq * 16))[i];
                    const uint32_t ns = sb + (uint32_t)((kb + 1) & 1) * PSTG;
#pragma unroll
                    for (int j = 0; j < 2; j++) {
                        cpa16(ns + 20480 + ldB + j * 16, BhG + bRowB + ko * 2 + lq * 32 + j * 16);
                        if (z < 2)
                            cpa16(ns + 30720 + ldB + j * 16, BlG + bRowB + ko * 2 + lq * 32 + j * 16);
                    }
                    CP_COMMIT();
                }

#pragma unroll
                for (int c2 = 0; c2 < 2; c2++) {
                    uint32_t ah[2][4], al[2][4];
#pragma unroll
                    for (int mb2 = 0; mb2 < 2; mb2++) {
                        ldm_x4(sb + stg + aBase + mb2 * 1280 + c2 * 32, ah[mb2]);
                        if (z < 2)
                            ldm_x4(sb + stg + 10240 + aBase + mb2 * 1280 + c2 * 32, al[mb2]);
                    }
#pragma unroll
                    for (int jj = 0; jj < 4; jj++) {
                        uint32_t r4[4];
                        ldm_x4(sb + stg + 20480 + bBase + jj * 1280 + c2 * 32, r4);
#pragma unroll
                        for (int mb2 = 0; mb2 < 2; mb2++) {
                            mma_f16(c[mb2][2 * jj], ah[mb2], r4[0], r4[1]);
                            mma_f16(c[mb2][2 * jj + 1], ah[mb2], r4[2], r4[3]);
                            if (z < 2) {
                                mma_f16(c[mb2][2 * jj], al[mb2], r4[0], r4[1]);
                                mma_f16(c[mb2][2 * jj + 1], al[mb2], r4[2], r4[3]);
                            }
                        }
                    }
                    if (z < 2) {
#pragma unroll
                        for (int jj = 0; jj < 4; jj++) {
                            uint32_t r4[4];
                            ldm_x4(sb + stg + 30720 + bBase + jj * 1280 + c2 * 32, r4);
#pragma unroll
                            for (int mb2 = 0; mb2 < 2; mb2++) {
                                mma_f16(c[mb2][2 * jj], ah[mb2], r4[0], r4[1]);
                                mma_f16(c[mb2][2 * jj + 1], ah[mb2], r4[2], r4[3]);
                            }
                        }
                    }
                }

                if (more) {
                    store_splitA(a, smc + (size_t)((kb + 1) & 1) * PSTG, ldB, z);
                    CP_WAIT0();
                    __syncthreads();
                }
            }

            // epilogue + per-(nb, batch) completion signal
#pragma unroll
            for (int mb2 = 0; mb2 < 2; mb2++) {
#pragma unroll
                for (int j = 0; j < 8; j++) {
                    const int R0 = m0 + wm * 32 + mb2 * 16 + g;
                    const int col = n0 + wn * 64 + 8 * j + 2 * t4;
                    if (z < 2) {
                        uint32_t hi, lo;
                        split2h(c[mb2][j][0], c[mb2][j][1], hi, lo);
                        *(uint32_t*)(Ch + (size_t)R0 * DMODEL + col) = hi;
                        *(uint32_t*)(Cl + (size_t)R0 * DMODEL + col) = lo;
                        split2h(c[mb2][j][2], c[mb2][j][3], hi, lo);
                        *(uint32_t*)(Ch + (size_t)(R0 + 8) * DMODEL + col) = hi;
                        *(uint32_t*)(Cl + (size_t)(R0 + 8) * DMODEL + col) = lo;
                    } else {
                        *(uint32_t*)(Ch + (size_t)R0 * DMODEL + col) =
                            pack_h2(c[mb2][j][0], c[mb2][j][1]);
                        *(uint32_t*)(Ch + (size_t)(R0 + 8) * DMODEL + col) =
                            pack_h2(c[mb2][j][2], c[mb2][j][3]);
                    }
                }
            }
            __threadfence();
            __syncthreads();
            if (tid == 0) atomicAdd(&g_done[nb * 2 + (mb >> 4)], 1u);

        } else {
            // ============== ATTN unit (128 Q rows), per-(nb,b) dep spin ==============
            const int aidx = u - N_PROJ;
            const int nb = aidx >> 6;
            const int r2 = aidx & 63;
            const int h = nb * 2 + (r2 >> 5);
            const int rb = r2 & 31;
            const int b = rb >> 4;
            const int q0 = (rb & 15) * 128;
            const int hoff = h * HDIM;

            if (tid == 0) {
                while (*(volatile unsigned*)&g_done[nb * 2 + b] < 48u) {}
            }
            __syncthreads();

            const int w = wid;
            const int lr2 = tid >> 1, lq2 = tid & 1;
            const int lr4 = tid >> 2, lq4 = tid & 3;
            const uint32_t ldQ = lr2 * 144 + lq2 * 64;
            const uint32_t ldKV = lr4 * 144 + lq4 * 32;
            const uint32_t qBase = (uint32_t)(16 * w + (lane & 15)) * 144 + (lane >> 4) * 16;
            const uint32_t kBase = (uint32_t)((lane & 7) + ((lane >> 4) << 3)) * 144
                                   + ((lane >> 3) & 1) * 16;
            const uint32_t vBase = (uint32_t)((lane & 7) + (((lane >> 3) & 1) << 3)) * 144
                                   + (lane >> 4) * 16;

            // prologue: Q (2 planes, persistent) + KV tile 0 -> stage 0
            {
                const size_t gQ = ((size_t)(b * SEQ + q0 + lr2) * DMODEL + hoff) * 2 + lq2 * 64;
                const size_t gB = ((size_t)(b * SEQ + lr4) * DMODEL + hoff) * 2 + lq4 * 32;
                const uint32_t dQ = sb + ldQ;
                const uint32_t dKV = sb + A_STG0 + ldKV;
#pragma unroll
                for (int i = 0; i < 4; i++) {
                    cpa16(dQ + i * 16,        (const char*)g_Qh + gQ + i * 16);
                    cpa16(dQ + A_QL + i * 16, (const char*)g_Ql + gQ + i * 16);
                }
#pragma unroll
                for (int i = 0; i < 2; i++) {
                    cpa16(dKV + i * 16,         (const char*)g_Kh + gB + i * 16);
                    cpa16(dKV + 9216 + i * 16,  (const char*)g_Kl + gB + i * 16);
                    cpa16(dKV + 18432 + i * 16, (const char*)g_Vh + gB + i * 16);
                }
                CP_COMMIT();
            }
            CP_WAIT0();
            __syncthreads();

            float m0 = -1e30f, m1 = -1e30f;
            float O[8][4];
            float lacc[4];
#pragma unroll
            for (int j = 0; j < 8; j++)
#pragma unroll
                for (int i = 0; i < 4; i++) O[j][i] = 0.0f;
#pragma unroll
            for (int i = 0; i < 4; i++) lacc[i] = 0.0f;

            for (int kt = 0; kt < SEQ / 64; kt++) {
                const uint32_t kv = sb + A_STG0 + (uint32_t)(kt & 1) * A_STGSZ;

                if (kt + 1 < SEQ / 64) {
                    const size_t gB = ((size_t)(b * SEQ + (kt + 1) * 64 + lr4) * DMODEL + hoff) * 2 + lq4 * 32;
                    const uint32_t d = sb + A_STG0 + (uint32_t)((kt + 1) & 1) * A_STGSZ + ldKV;
#pragma unroll
                    for (int i = 0; i < 2; i++) {
                        cpa16(d + i * 16,         (const char*)g_Kh + gB + i * 16);
                        cpa16(d + 9216 + i * 16,  (const char*)g_Kl + gB + i * 16);
                        cpa16(d + 18432 + i * 16, (const char*)g_Vh + gB + i * 16);
                    }
                    CP_COMMIT();
                }

                // ---- S (scoped) -> P packed fp16 + alphas ----
                uint32_t P[8][2];
                float al0, al1;
                {
                    float S[8][4];
#pragma unroll
                    for (int j = 0; j < 8; j++)
#pragma unroll
                        for (int i = 0; i < 4; i++) S[j][i] = 0.0f;

#pragma unroll
                    for (int c = 0; c < 4; c++) {
                        uint32_t aqh[4], aql[4];
                        ldm_x4(sb + qBase + c * 32, aqh);
                        ldm_x4(sb + A_QL + qBase + c * 32, aql);
#pragma unroll
                        for (int jj = 0; jj < 4; jj++) {
                            uint32_t kh[4], kl[4];
                            ldm_x4(kv + kBase + jj * 2304 + c * 32, kh);
                            ldm_x4(kv + 9216 + kBase + jj * 2304 + c * 32, kl);
                            mma_f16(S[2 * jj], aqh, kh[0], kh[1]);
                            mma_f16(S[2 * jj + 1], aqh, kh[2], kh[3]);
                            mma_f16(S[2 * jj], aql, kh[0], kh[1]);
                            mma_f16(S[2 * jj + 1], aql, kh[2], kh[3]);
                            mma_f16(S[2 * jj], aqh, kl[0], kl[1]);
                            mma_f16(S[2 * jj + 1], aqh, kl[2], kl[3]);
                        }
                    }

                    float mx0 = -1e30f, mx1 = -1e30f;
#pragma unroll
                    for (int j = 0; j < 8; j++) {
                        mx0 = fmaxf(mx0, fmaxf(S[j][0], S[j][1]));
                        mx1 = fmaxf(mx1, fmaxf(S[j][2], S[j][3]));
                    }
                    mx0 = fmaxf(mx0, __shfl_xor_sync(0xffffffffu, mx0, 1));
                    mx0 = fmaxf(mx0, __shfl_xor_sync(0xffffffffu, mx0, 2));
                    mx1 = fmaxf(mx1, __shfl_xor_sync(0xffffffffu, mx1, 1));
                    mx1 = fmaxf(mx1, __shfl_xor_sync(0xffffffffu, mx1, 2));
                    const float mn0 = fmaxf(m0, mx0), mn1 = fmaxf(m1, mx1);
                    al0 = ex2((m0 - mn0) * CEXP);
                    al1 = ex2((m1 - mn1) * CEXP);
                    m0 = mn0; m1 = mn1;
                    const float mc0 = m0 * CEXP;
                    const float mc1 = m1 * CEXP;

#pragma unroll
                    for (int j = 0; j < 8; j++) {
                        float x0 = fmaf(S[j][0], CEXP, -mc0);
                        float x1 = fmaf(S[j][1], CEXP, -mc0);
                        float x2 = fmaf(S[j][2], CEXP, -mc1);
                        float x3 = fmaf(S[j][3], CEXP, -mc1);
                        P[j][0] = h2ex2(pack_h2(x0, x1));
                        P[j][1] = h2ex2(pack_h2(x2, x3));
                    }
                }   // S dead here

#pragma unroll
                for (int j = 0; j < 8; j++) {
                    O[j][0] *= al0; O[j][1] *= al0;
                    O[j][2] *= al1; O[j][3] *= al1;
                }
                lacc[0] *= al0; lacc[1] *= al0;
                lacc[2] *= al1; lacc[3] *= al1;

                // ---- O += P V ; l += P @ ones ----
#pragma unroll
                for (int c = 0; c < 4; c++) {
                    uint32_t ph[4];
                    ph[0] = P[2 * c][0];
                    ph[1] = P[2 * c][1];
                    ph[2] = P[2 * c + 1][0];
                    ph[3] = P[2 * c + 1][1];
                    mma_f16(lacc, ph, ONE2, ONE2);
#pragma unroll
                    for (int jj = 0; jj < 4; jj++) {
                        uint32_t r4[4];
                        ldm_x4t(kv + 18432 + vBase + c * 2304 + jj * 32, r4);
                        mma_f16(O[2 * jj], ph, r4[0], r4[1]);
                        mma_f16(O[2 * jj + 1], ph, r4[2], r4[3]);
                    }
                }

                if (kt + 1 < SEQ / 64) {
                    CP_WAIT0();
                    __syncthreads();
                }
            }

            // ---- epilogue ----
            const float i0 = 1.0f / lacc[0];
            const float i1 = 1.0f / lacc[2];
            const size_t R0 = (size_t)(b * SEQ + q0 + 16 * w + g);
#pragma unroll
            for (int j = 0; j < 8; j++) {
                const int col = hoff + 8 * j + 2 * t4;
                *(float2*)&out[R0 * DMODEL + col] = make_float2(O[j][0] * i0, O[j][1] * i0);
                *(float2*)&out[(R0 + 8) * DMODEL + col] = make_float2(O[j][2] * i1, O[j][3] * i1);
            }
        }
    }

    // ---------------- Self-reset for graph replays ----------------
    __syncthreads();
    if (tid == 0) {
        unsigned f = atomicAdd(&g_fin, 1u);
        if (f == (unsigned)gridDim.x - 1u) {
            g_ctr = 0u;
            g_bar_w = 0u;
            g_fin = 0u;
#pragma unroll
            for (int i = 0; i < 16; i++) g_done[i] = 0u;
            __threadfence();
        }
    }
}

// ===========================================================================
// kernel_launch
// ===========================================================================
extern "C" void kernel_launch(void* const* d_in, const int* in_sizes, int n_in,
                              void* d_out, int out_size)
{
    const float* q  = (const float*)d_in[0];
    const float* k  = (const float*)d_in[1];
    const float* v  = (const float*)d_in[2];
    const float* Wq = (const float*)d_in[3];
    const float* Wk = (const float*)d_in[4];
    const float* Wv = (const float*)d_in[5];
    float* out = (float*)d_out;

    int nsm = 148;
    cudaDeviceGetAttribute(&nsm, cudaDevAttrMultiProcessorCount, 0);
    const int grid = nsm * 2;   // exactly co-resident at 2 CTAs/SM

    cudaFuncSetAttribute(fused_mma, cudaFuncAttributeMaxDynamicSharedMemorySize, FUSED_SMEM);
    fused_mma<<<grid, 256, FUSED_SMEM>>>(q, k, v, Wq, Wk, Wv, out);
}

// round 17
// speedup vs baseline: 1.1400x; 1.0552x over previous
#include <cuda_runtime.h>
#include <cuda_fp16.h>
#include <cstdint>

// Problem constants
#define BATCH   2
#define SEQ     2048
#define DMODEL  1024
#define NHEADS  16
#define HDIM    64
#define CEXP    92.33248261689366f   // SCALE(=64) * log2(e)
#define NELEM   (BATCH * SEQ * DMODEL)

// Scratch
__device__ __half g_WT_hi[3 * DMODEL * DMODEL];
__device__ __half g_WT_lo[3 * DMODEL * DMODEL];
__device__ __half g_Qh[NELEM];
__device__ __half g_Ql[NELEM];
__device__ __half g_Kh[NELEM];
__device__ __half g_Kl[NELEM];
__device__ __half g_Vh[NELEM];
__device__ unsigned g_ctr;        // pooled work queue
__device__ unsigned g_bar_w;      // global barrier after W phase
__device__ unsigned g_done[8];    // proj completion per n-block (target 96)
__device__ unsigned g_fin;        // finish counter (self-reset)

// Split-KV scratch: last NSPLIT attn q-tiles computed in 2 halves.
#define NSPLIT     240
#define SPLIT_BASE 272
__device__ float g_Op[2][NSPLIT][128][64];   // unnormalized O
__device__ float g_Om[2][NSPLIT][128];       // row max (raw)
__device__ float g_Ol[2][NSPLIT][128];       // row l (partial)

// ===========================================================================
// Helpers (sm_80-era PTX only)
// ===========================================================================
__device__ __forceinline__ uint32_t smem_u32(const void* p) {
    uint32_t a;
    asm("{ .reg .u64 t; cvta.to.shared.u64 t, %1; cvt.u32.u64 %0, t; }" : "=r"(a) : "l"(p));
    return a;
}
__device__ __forceinline__ void ldm_x4(uint32_t addr, uint32_t* r) {
    asm volatile("ldmatrix.sync.aligned.m8n8.x4.shared.b16 {%0,%1,%2,%3}, [%4];"
                 : "=r"(r[0]), "=r"(r[1]), "=r"(r[2]), "=r"(r[3]) : "r"(addr));
}
__device__ __forceinline__ void ldm_x4t(uint32_t addr, uint32_t* r) {
    asm volatile("ldmatrix.sync.aligned.m8n8.x4.trans.shared.b16 {%0,%1,%2,%3}, [%4];"
                 : "=r"(r[0]), "=r"(r[1]), "=r"(r[2]), "=r"(r[3]) : "r"(addr));
}
__device__ __forceinline__ void mma_f16(float* c, const uint32_t* a, uint32_t b0, uint32_t b1) {
    asm volatile("mma.sync.aligned.m16n8k16.row.col.f32.f16.f16.f32 "
                 "{%0,%1,%2,%3}, {%4,%5,%6,%7}, {%8,%9}, {%0,%1,%2,%3};"
                 : "+f"(c[0]), "+f"(c[1]), "+f"(c[2]), "+f"(c[3])
                 : "r"(a[0]), "r"(a[1]), "r"(a[2]), "r"(a[3]), "r"(b0), "r"(b1));
}
__device__ __forceinline__ uint32_t pack_h2(float p0, float p1) {
    uint32_t h;
    asm("cvt.rn.f16x2.f32 %0, %1, %2;" : "=r"(h) : "f"(p1), "f"(p0));
    return h;
}
__device__ __forceinline__ void split2h(float p0, float p1, uint32_t& hi, uint32_t& lo) {
    uint32_t h = pack_h2(p0, p1);
    float f0, f1;
    asm("{.reg .b16 a,b; mov.b32 {a,b}, %2; cvt.f32.f16 %0, a; cvt.f32.f16 %1, b;}"
        : "=f"(f0), "=f"(f1) : "r"(h));
    hi = h;
    lo = pack_h2(p0 - f0, p1 - f1);
}
__device__ __forceinline__ float ex2(float x) {
    float r;
    asm("ex2.approx.f32 %0, %1;" : "=f"(r) : "f"(x));
    return r;
}
__device__ __forceinline__ uint32_t h2ex2(uint32_t x) {
    uint32_t r;
    asm("ex2.approx.f16x2 %0, %1;" : "=r"(r) : "r"(x));
    return r;
}
__device__ __forceinline__ void cpa16(uint32_t s, const void* g) {
    asm volatile("cp.async.cg.shared.global [%0], [%1], 16;" :: "r"(s), "l"(g));
}
#define CP_COMMIT() asm volatile("cp.async.commit_group;" ::: "memory")
#define CP_WAIT0()  asm volatile("cp.async.wait_group 0;" ::: "memory")

#define ONE2 0x3C003C00u   // fp16x2 {1.0, 1.0}

// Proj smem layout: AH 0, AL 10240, BH 20480, BL 30720; stage size 40960
#define PSTG    40960
// Attn smem layout: QH 0, QL 18432; stage s at 36864 + s*27648 {KH, KL+9216, VH+18432}
#define A_QL    18432
#define A_STG0  36864
#define A_STGSZ 27648
#define FUSED_SMEM 92176
#define SU_OFF  92160

#define N_PROJ   768
#define N_AFULL  272
#define N_UNITS  1520   // 768 proj + 272 full attn + 480 attn halves = 5 * 304

__device__ __forceinline__ void store_splitA(const float4* a, char* dst_stage,
                                             uint32_t ldB, int z)
{
    uint32_t hb[8], lb[8];
#pragma unroll
    for (int i = 0; i < 4; i++) {
        split2h(a[i].x, a[i].y, hb[2 * i], lb[2 * i]);
        split2h(a[i].z, a[i].w, hb[2 * i + 1], lb[2 * i + 1]);
    }
    char* dh = dst_stage + ldB;
    ((uint4*)dh)[0] = make_uint4(hb[0], hb[1], hb[2], hb[3]);
    ((uint4*)dh)[1] = make_uint4(hb[4], hb[5], hb[6], hb[7]);
    if (z < 2) {
        char* dl = dst_stage + 10240 + ldB;
        ((uint4*)dl)[0] = make_uint4(lb[0], lb[1], lb[2], lb[3]);
        ((uint4*)dl)[1] = make_uint4(lb[4], lb[5], lb[6], lb[7]);
    }
}

// ===========================================================================
// Fused persistent kernel
// ===========================================================================
__global__ __launch_bounds__(256, 2) void fused_mma(
    const float* __restrict__ qi, const float* __restrict__ ki,
    const float* __restrict__ vi,
    const float* __restrict__ Wq, const float* __restrict__ Wk,
    const float* __restrict__ Wv, float* __restrict__ out)
{
    extern __shared__ char smc[];
    const uint32_t sb = smem_u32(smc);
    int* suq = (int*)(smc + SU_OFF);
    const int tid = threadIdx.x;
    const int lane = tid & 31;
    const int wid = tid >> 5;
    const int g = lane >> 2, t4 = lane & 3;

    // ---------------- Phase 0: W transpose + split-fp16 ----------------
    {
        float (*tile)[33] = (float(*)[33])smc;
        const int tx = tid & 31, ty = tid >> 5;
        for (int t = blockIdx.x; t < 3072; t += gridDim.x) {
            const int z = t >> 10;
            const int rem = t & 1023;
            const int k0 = (rem >> 5) * 32;
            const int n0 = (rem & 31) * 32;
            const float* W = (z == 0) ? Wq : (z == 1) ? Wk : Wv;
            __syncthreads();
#pragma unroll
            for (int i = 0; i < 4; i++)
                tile[ty + i * 8][tx] = W[(size_t)(k0 + ty + i * 8) * DMODEL + n0 + tx];
            __syncthreads();
            const size_t base = (size_t)z * DMODEL * DMODEL;
#pragma unroll
            for (int i = 0; i < 4; i++) {
                const int n = n0 + ty + i * 8;
                const int k = k0 + tx;
                const float v = tile[tx][ty + i * 8];
                __half h = __float2half_rn(v);
                g_WT_hi[base + (size_t)n * DMODEL + k] = h;
                g_WT_lo[base + (size_t)n * DMODEL + k] = __float2half_rn(v - __half2float(h));
            }
        }
        __threadfence();
        __syncthreads();
        if (tid == 0) {
            atomicAdd(&g_bar_w, 1u);
            while (*(volatile unsigned*)&g_bar_w < (unsigned)gridDim.x) {}
        }
        __syncthreads();
    }

    // ---------------- Pooled work queue ----------------
    while (true) {
        if (tid == 0) *suq = (int)atomicAdd(&g_ctr, 1u);
        __syncthreads();
        const int u = *suq;
        if (u >= N_UNITS) break;

        if (u < N_PROJ) {
            // ============== PROJ unit (128m x 128n x 1024k), nb-major ==============
            const int nb = u / 96;
            const int r = u - nb * 96;
            const int z = r >> 5;
            const int m0 = (r & 31) * 128;
            const int n0 = nb * 128;

            const int wm = wid & 3, wn = wid >> 2;
            const uint32_t aBase = (uint32_t)(wm * 32 + (lane & 15)) * 80 + (lane >> 4) * 16;
            const uint32_t bBase = (uint32_t)(wn * 64 + (lane & 7) + ((lane >> 4) << 3)) * 80
                                   + ((lane >> 3) & 1) * 16;
            const int lr = tid >> 1, lq = tid & 1;
            const uint32_t ldB = lr * 80 + lq * 32;

            const float* A;
            __half *Ch, *Cl;
            if (z == 0)      { A = qi; Ch = g_Qh; Cl = g_Ql; }
            else if (z == 1) { A = ki; Ch = g_Kh; Cl = g_Kl; }
            else             { A = vi; Ch = g_Vh; Cl = 0; }
            const size_t woff = (size_t)z * DMODEL * DMODEL;
            const char* BhG = (const char*)(g_WT_hi + woff);
            const char* BlG = (const char*)(g_WT_lo + woff);
            const size_t aRow = (size_t)(m0 + lr) * DMODEL;
            const size_t bRowB = (size_t)(n0 + lr) * DMODEL * 2;

            float c[2][8][4];
#pragma unroll
            for (int mb2 = 0; mb2 < 2; mb2++)
#pragma unroll
                for (int j = 0; j < 8; j++)
#pragma unroll
                    for (int i = 0; i < 4; i++) c[mb2][j][i] = 0.0f;

            float4 a[4];
#pragma unroll
            for (int i = 0; i < 4; i++)
                a[i] = ((const float4*)(A + aRow + lq * 16))[i];
#pragma unroll
            for (int j = 0; j < 2; j++) {
                cpa16(sb + 20480 + ldB + j * 16, BhG + bRowB + lq * 32 + j * 16);
                if (z < 2)
                    cpa16(sb + 30720 + ldB + j * 16, BlG + bRowB + lq * 32 + j * 16);
            }
            CP_COMMIT();
            store_splitA(a, smc, ldB, z);
            CP_WAIT0();
            __syncthreads();

            for (int kb = 0; kb < 32; kb++) {
                const uint32_t stg = (uint32_t)(kb & 1) * PSTG;
                const bool more = (kb + 1 < 32);
                if (more) {
                    const int ko = (kb + 1) * 32;
#pragma unroll
                    for (int i = 0; i < 4; i++)
                        a[i] = ((const float4*)(A + aRow + ko + lq * 16))[i];
                    const uint32_t ns = sb + (uint32_t)((kb + 1) & 1) * PSTG;
#pragma unroll
                    for (int j = 0; j < 2; j++) {
                        cpa16(ns + 20480 + ldB + j * 16, BhG + bRowB + ko * 2 + lq * 32 + j * 16);
                        if (z < 2)
                            cpa16(ns + 30720 + ldB + j * 16, BlG + bRowB + ko * 2 + lq * 32 + j * 16);
                    }
                    CP_COMMIT();
                }

#pragma unroll
                for (int c2 = 0; c2 < 2; c2++) {
                    uint32_t ah[2][4], al[2][4];
#pragma unroll
                    for (int mb2 = 0; mb2 < 2; mb2++) {
                        ldm_x4(sb + stg + aBase + mb2 * 1280 + c2 * 32, ah[mb2]);
                        if (z < 2)
                            ldm_x4(sb + stg + 10240 + aBase + mb2 * 1280 + c2 * 32, al[mb2]);
                    }
#pragma unroll
                    for (int jj = 0; jj < 4; jj++) {
                        uint32_t r4[4];
                        ldm_x4(sb + stg + 20480 + bBase + jj * 1280 + c2 * 32, r4);
#pragma unroll
                        for (int mb2 = 0; mb2 < 2; mb2++) {
                            mma_f16(c[mb2][2 * jj], ah[mb2], r4[0], r4[1]);
                            mma_f16(c[mb2][2 * jj + 1], ah[mb2], r4[2], r4[3]);
                            if (z < 2) {
                                mma_f16(c[mb2][2 * jj], al[mb2], r4[0], r4[1]);
                                mma_f16(c[mb2][2 * jj + 1], al[mb2], r4[2], r4[3]);
                            }
                        }
                    }
                    if (z < 2) {
#pragma unroll
                        for (int jj = 0; jj < 4; jj++) {
                            uint32_t r4[4];
                            ldm_x4(sb + stg + 30720 + bBase + jj * 1280 + c2 * 32, r4);
#pragma unroll
                            for (int mb2 = 0; mb2 < 2; mb2++) {
                                mma_f16(c[mb2][2 * jj], ah[mb2], r4[0], r4[1]);
                                mma_f16(c[mb2][2 * jj + 1], ah[mb2], r4[2], r4[3]);
                            }
                        }
                    }
                }

                if (more) {
                    store_splitA(a, smc + (size_t)((kb + 1) & 1) * PSTG, ldB, z);
                    CP_WAIT0();
                    __syncthreads();
                }
            }

            // epilogue + per-nb completion signal
#pragma unroll
            for (int mb2 = 0; mb2 < 2; mb2++) {
#pragma unroll
                for (int j = 0; j < 8; j++) {
                    const int R0 = m0 + wm * 32 + mb2 * 16 + g;
                    const int col = n0 + wn * 64 + 8 * j + 2 * t4;
                    if (z < 2) {
                        uint32_t hi, lo;
                        split2h(c[mb2][j][0], c[mb2][j][1], hi, lo);
                        *(uint32_t*)(Ch + (size_t)R0 * DMODEL + col) = hi;
                        *(uint32_t*)(Cl + (size_t)R0 * DMODEL + col) = lo;
                        split2h(c[mb2][j][2], c[mb2][j][3], hi, lo);
                        *(uint32_t*)(Ch + (size_t)(R0 + 8) * DMODEL + col) = hi;
                        *(uint32_t*)(Cl + (size_t)(R0 + 8) * DMODEL + col) = lo;
                    } else {
                        *(uint32_t*)(Ch + (size_t)R0 * DMODEL + col) =
                            pack_h2(c[mb2][j][0], c[mb2][j][1]);
                        *(uint32_t*)(Ch + (size_t)(R0 + 8) * DMODEL + col) =
                            pack_h2(c[mb2][j][2], c[mb2][j][3]);
                    }
                }
            }
            __threadfence();
            __syncthreads();
            if (tid == 0) atomicAdd(&g_done[nb], 1u);

        } else {
            // ============== ATTN unit: full (32 KV tiles) or half (16) ==============
            int tile, kt_beg, kt_end, half_s = 0;
            bool is_half;
            if (u < N_PROJ + N_AFULL) {
                tile = u - N_PROJ;
                kt_beg = 0; kt_end = 32; is_half = false;
            } else {
                const int hidx = u - (N_PROJ + N_AFULL);
                tile = SPLIT_BASE + (hidx >> 1);
                half_s = hidx & 1;
                kt_beg = half_s * 16; kt_end = kt_beg + 16; is_half = true;
            }
            const int nb = tile >> 6;
            const int h = nb * 2 + ((tile >> 5) & 1);
            const int b = (tile >> 4) & 1;
            const int q0 = (tile & 15) * 128;
            const int hoff = h * HDIM;

            if (tid == 0) {
                while (*(volatile unsigned*)&g_done[nb] < 96u) {}
            }
            __syncthreads();

            const int w = wid;
            const int lr2 = tid >> 1, lq2 = tid & 1;
            const int lr4 = tid >> 2, lq4 = tid & 3;
            const uint32_t ldQ = lr2 * 144 + lq2 * 64;
            const uint32_t ldKV = lr4 * 144 + lq4 * 32;
            const uint32_t qBase = (uint32_t)(16 * w + (lane & 15)) * 144 + (lane >> 4) * 16;
            const uint32_t kBase = (uint32_t)((lane & 7) + ((lane >> 4) << 3)) * 144
                                   + ((lane >> 3) & 1) * 16;
            const uint32_t vBase = (uint32_t)((lane & 7) + (((lane >> 3) & 1) << 3)) * 144
                                   + (lane >> 4) * 16;

            // prologue: Q (2 planes, persistent) + KV tile kt_beg -> stage 0
            {
                const size_t gQ = ((size_t)(b * SEQ + q0 + lr2) * DMODEL + hoff) * 2 + lq2 * 64;
                const size_t gB = ((size_t)(b * SEQ + kt_beg * 64 + lr4) * DMODEL + hoff) * 2 + lq4 * 32;
                const uint32_t dQ = sb + ldQ;
                const uint32_t dKV = sb + A_STG0 + ldKV;
#pragma unroll
                for (int i = 0; i < 4; i++) {
                    cpa16(dQ + i * 16,        (const char*)g_Qh + gQ + i * 16);
                    cpa16(dQ + A_QL + i * 16, (const char*)g_Ql + gQ + i * 16);
                }
#pragma unroll
                for (int i = 0; i < 2; i++) {
                    cpa16(dKV + i * 16,         (const char*)g_Kh + gB + i * 16);
                    cpa16(dKV + 9216 + i * 16,  (const char*)g_Kl + gB + i * 16);
                    cpa16(dKV + 18432 + i * 16, (const char*)g_Vh + gB + i * 16);
                }
                CP_COMMIT();
            }
            CP_WAIT0();
            __syncthreads();

            float m0 = -1e30f, m1 = -1e30f;
            float O[8][4];
            float lacc[4];
#pragma unroll
            for (int j = 0; j < 8; j++)
#pragma unroll
                for (int i = 0; i < 4; i++) O[j][i] = 0.0f;
#pragma unroll
            for (int i = 0; i < 4; i++) lacc[i] = 0.0f;

            for (int kt = kt_beg; kt < kt_end; kt++) {
                const uint32_t kv = sb + A_STG0 + (uint32_t)(kt & 1) * A_STGSZ;

                if (kt + 1 < kt_end) {
                    const size_t gB = ((size_t)(b * SEQ + (kt + 1) * 64 + lr4) * DMODEL + hoff) * 2 + lq4 * 32;
                    const uint32_t d = sb + A_STG0 + (uint32_t)((kt + 1) & 1) * A_STGSZ + ldKV;
#pragma unroll
                    for (int i = 0; i < 2; i++) {
                        cpa16(d + i * 16,         (const char*)g_Kh + gB + i * 16);
                        cpa16(d + 9216 + i * 16,  (const char*)g_Kl + gB + i * 16);
                        cpa16(d + 18432 + i * 16, (const char*)g_Vh + gB + i * 16);
                    }
                    CP_COMMIT();
                }

                // ---- S (scoped) -> P packed fp16 + alphas ----
                uint32_t P[8][2];
                float al0, al1;
                {
                    float S[8][4];
#pragma unroll
                    for (int j = 0; j < 8; j++)
#pragma unroll
                        for (int i = 0; i < 4; i++) S[j][i] = 0.0f;

#pragma unroll
                    for (int c = 0; c < 4; c++) {
                        uint32_t aqh[4], aql[4];
                        ldm_x4(sb + qBase + c * 32, aqh);
                        ldm_x4(sb + A_QL + qBase + c * 32, aql);
#pragma unroll
                        for (int jj = 0; jj < 4; jj++) {
                            uint32_t kh[4], kl[4];
                            ldm_x4(kv + kBase + jj * 2304 + c * 32, kh);
                            ldm_x4(kv + 9216 + kBase + jj * 2304 + c * 32, kl);
                            mma_f16(S[2 * jj], aqh, kh[0], kh[1]);
                            mma_f16(S[2 * jj + 1], aqh, kh[2], kh[3]);
                            mma_f16(S[2 * jj], aql, kh[0], kh[1]);
                            mma_f16(S[2 * jj + 1], aql, kh[2], kh[3]);
                            mma_f16(S[2 * jj], aqh, kl[0], kl[1]);
                            mma_f16(S[2 * jj + 1], aqh, kl[2], kl[3]);
                        }
                    }

                    float mx0 = -1e30f, mx1 = -1e30f;
#pragma unroll
                    for (int j = 0; j < 8; j++) {
                        mx0 = fmaxf(mx0, fmaxf(S[j][0], S[j][1]));
                        mx1 = fmaxf(mx1, fmaxf(S[j][2], S[j][3]));
                    }
                    mx0 = fmaxf(mx0, __shfl_xor_sync(0xffffffffu, mx0, 1));
                    mx0 = fmaxf(mx0, __shfl_xor_sync(0xffffffffu, mx0, 2));
                    mx1 = fmaxf(mx1, __shfl_xor_sync(0xffffffffu, mx1, 1));
                    mx1 = fmaxf(mx1, __shfl_xor_sync(0xffffffffu, mx1, 2));
                    const float mn0 = fmaxf(m0, mx0), mn1 = fmaxf(m1, mx1);
                    al0 = ex2((m0 - mn0) * CEXP);
                    al1 = ex2((m1 - mn1) * CEXP);
                    m0 = mn0; m1 = mn1;
                    const float mc0 = m0 * CEXP;
                    const float mc1 = m1 * CEXP;

#pragma unroll
                    for (int j = 0; j < 8; j++) {
                        float x0 = fmaf(S[j][0], CEXP, -mc0);
                        float x1 = fmaf(S[j][1], CEXP, -mc0);
                        float x2 = fmaf(S[j][2], CEXP, -mc1);
                        float x3 = fmaf(S[j][3], CEXP, -mc1);
                        P[j][0] = h2ex2(pack_h2(x0, x1));
                        P[j][1] = h2ex2(pack_h2(x2, x3));
                    }
                }   // S dead here

#pragma unroll
                for (int j = 0; j < 8; j++) {
                    O[j][0] *= al0; O[j][1] *= al0;
                    O[j][2] *= al1; O[j][3] *= al1;
                }
                lacc[0] *= al0; lacc[1] *= al0;
                lacc[2] *= al1; lacc[3] *= al1;

                // ---- O += P V ; l += P @ ones ----
#pragma unroll
                for (int c = 0; c < 4; c++) {
                    uint32_t ph[4];
                    ph[0] = P[2 * c][0];
                    ph[1] = P[2 * c][1];
                    ph[2] = P[2 * c + 1][0];
                    ph[3] = P[2 * c + 1][1];
                    mma_f16(lacc, ph, ONE2, ONE2);
#pragma unroll
                    for (int jj = 0; jj < 4; jj++) {
                        uint32_t r4[4];
                        ldm_x4t(kv + 18432 + vBase + c * 2304 + jj * 32, r4);
                        mma_f16(O[2 * jj], ph, r4[0], r4[1]);
                        mma_f16(O[2 * jj + 1], ph, r4[2], r4[3]);
                    }
                }

                if (kt + 1 < kt_end) {
                    CP_WAIT0();
                    __syncthreads();
                }
            }

            // ---- epilogue ----
            if (!is_half) {
                const float i0 = 1.0f / lacc[0];
                const float i1 = 1.0f / lacc[2];
                const size_t R0 = (size_t)(b * SEQ + q0 + 16 * w + g);
#pragma unroll
                for (int j = 0; j < 8; j++) {
                    const int col = hoff + 8 * j + 2 * t4;
                    *(float2*)&out[R0 * DMODEL + col] = make_float2(O[j][0] * i0, O[j][1] * i0);
                    *(float2*)&out[(R0 + 8) * DMODEL + col] = make_float2(O[j][2] * i1, O[j][3] * i1);
                }
            } else {
                const int ti = tile - SPLIT_BASE;
                const int row0 = 16 * w + g;
                float* Op = &g_Op[half_s][ti][0][0];
#pragma unroll
                for (int j = 0; j < 8; j++) {
                    const int col = 8 * j + 2 * t4;
                    *(float2*)&Op[row0 * 64 + col] = make_float2(O[j][0], O[j][1]);
                    *(float2*)&Op[(row0 + 8) * 64 + col] = make_float2(O[j][2], O[j][3]);
                }
                if (t4 == 0) {
                    g_Om[half_s][ti][row0] = m0;
                    g_Om[half_s][ti][row0 + 8] = m1;
                    g_Ol[half_s][ti][row0] = lacc[0];
                    g_Ol[half_s][ti][row0 + 8] = lacc[2];
                }
            }
        }
    }

    // ---------------- Self-reset for graph replays ----------------
    __syncthreads();
    if (tid == 0) {
        unsigned f = atomicAdd(&g_fin, 1u);
        if (f == (unsigned)gridDim.x - 1u) {
            g_ctr = 0u;
            g_bar_w = 0u;
            g_fin = 0u;
#pragma unroll
            for (int i = 0; i < 8; i++) g_done[i] = 0u;
            __threadfence();
        }
    }
}

// ===========================================================================
// Merge kernel: recombine split-KV halves for the NSPLIT tiles.
// ===========================================================================
__global__ __launch_bounds__(256) void merge_halves(float* __restrict__ out)
{
    const int ti = blockIdx.x;               // 0..NSPLIT-1
    const int tile = SPLIT_BASE + ti;
    const int nb = tile >> 6;
    const int h = nb * 2 + ((tile >> 5) & 1);
    const int b = (tile >> 4) & 1;
    const int q0 = (tile & 15) * 128;

    const int t = threadIdx.x;
    const int r = t >> 1;
    const int c0 = (t & 1) * 32;

    const float mA = g_Om[0][ti][r], mB = g_Om[1][ti][r];
    const float m = fmaxf(mA, mB);
    const float eA = ex2((mA - m) * CEXP);
    const float eB = ex2((mB - m) * CEXP);
    const float l = g_Ol[0][ti][r] * eA + g_Ol[1][ti][r] * eB;
    const float inv = 1.0f / l;

    const float* OA = &g_Op[0][ti][r][0];
    const float* OB = &g_Op[1][ti][r][0];
    float* dst = &out[(size_t)(b * SEQ + q0 + r) * DMODEL + h * HDIM];
#pragma unroll
    for (int c = 0; c < 32; c += 4) {
        float4 a4 = *(const float4*)(OA + c0 + c);
        float4 b4 = *(const float4*)(OB + c0 + c);
        *(float4*)(dst + c0 + c) = make_float4(
            (a4.x * eA + b4.x * eB) * inv, (a4.y * eA + b4.y * eB) * inv,
            (a4.z * eA + b4.z * eB) * inv, (a4.w * eA + b4.w * eB) * inv);
    }
}

// ===========================================================================
// kernel_launch
// ===========================================================================
extern "C" void kernel_launch(void* const* d_in, const int* in_sizes, int n_in,
                              void* d_out, int out_size)
{
    const float* q  = (const float*)d_in[0];
    const float* k  = (const float*)d_in[1];
    const float* v  = (const float*)d_in[2];
    const float* Wq = (const float*)d_in[3];
    const float* Wk = (const float*)d_in[4];
    const float* Wv = (const float*)d_in[5];
    float* out = (float*)d_out;

    int nsm = 148;
    cudaDeviceGetAttribute(&nsm, cudaDevAttrMultiProcessorCount, 0);
    const int grid = nsm * 2;   // exactly co-resident at 2 CTAs/SM

    cudaFuncSetAttribute(fused_mma, cudaFuncAttributeMaxDynamicSharedMemorySize, FUSED_SMEM);
    fused_mma<<<grid, 256, FUSED_SMEM>>>(q, k, v, Wq, Wk, Wv, out);
    merge_halves<<<NSPLIT, 256>>>(out);
}